// round 15
// baseline (speedup 1.0000x reference)
#include <cuda_runtime.h>

#define NN 10000
#define EE 300000
#define NPB 4   // nodes per edge-kernel block

// ---------------- scratch (__device__ globals, no allocs) ----------------
__device__ __align__(16) float g_h[NN * 32];
__device__ __align__(16) float g_k2[(size_t)EE * 256];
__device__ __align__(16) float g_G2[(size_t)NN * 8192];   // [n][c*32+i] node-major
__device__ __align__(16) float g_Bias[NN * 32];
__device__ __align__(16) float g_agg[NN * 32];
__device__ __align__(16) float g_cacc[NN * 3];
__device__ __align__(16) float g_coord[NN * 3];
__device__ __align__(16) float g_w2b[128 * 256];
__device__ __align__(16) float g_w2s[128 * 256];
__device__ __align__(16) float g_k3b[32 * 8192];   // [j][ci] tf32-big of ker3
__device__ __align__(16) float g_k3s[32 * 8192];   // [j][ci] tf32-small
__device__ float g_cntf[NN];
__device__ int   g_colcnt[NN];
__device__ int   g_rowcnt[NN];
__device__ int   g_cursor[NN];
__device__ int   g_colstart[NN + 1];
__device__ int   g_perm[EE];
__device__ int   g_is64;

// ---------------- tf32 / async helpers ----------------
__device__ __forceinline__ float tf32r(float f) {
    unsigned r;
    asm("cvt.rna.tf32.f32 %0, %1;" : "=r"(r) : "f"(f));
    return __uint_as_float(r);
}

__device__ __forceinline__ void mma_tf32(float* c, const unsigned* a, const unsigned* b) {
    asm volatile(
        "mma.sync.aligned.m16n8k8.row.col.f32.tf32.tf32.f32 "
        "{%0,%1,%2,%3}, {%4,%5,%6,%7}, {%8,%9}, {%0,%1,%2,%3};"
        : "+f"(c[0]), "+f"(c[1]), "+f"(c[2]), "+f"(c[3])
        : "r"(a[0]), "r"(a[1]), "r"(a[2]), "r"(a[3]), "r"(b[0]), "r"(b[1]));
}

__device__ __forceinline__ void cp_async16(void* smem_dst, const void* gmem_src) {
    unsigned s = (unsigned)__cvta_generic_to_shared(smem_dst);
    asm volatile("cp.async.cg.shared.global [%0], [%1], 16;\n" :: "r"(s), "l"(gmem_src));
}
#define CP_COMMIT() asm volatile("cp.async.commit_group;\n" ::)
#define CP_WAIT(N)  asm volatile("cp.async.wait_group %0;\n" :: "n"(N))

// ---------------- edge-index dtype handling ----------------
__global__ void detect_kernel(const void* __restrict__ ei) {
    const int* w = (const int*)ei;
    int lane = threadIdx.x;
    int hi = w[2 * lane + 1];
    unsigned any = __ballot_sync(0xffffffffu, hi != 0);
    if (lane == 0) g_is64 = (any == 0u) ? 1 : 0;
}

__device__ __forceinline__ int eidx(const void* __restrict__ ei, long long pos, int is64) {
    int v = is64 ? (int)((const long long*)ei)[pos] : ((const int*)ei)[pos];
    return min(max(v, 0), NN - 1);
}

// ---------------- small utility kernels ----------------
__global__ void zero_sort_kernel() {
    int i = blockIdx.x * blockDim.x + threadIdx.x;
    if (i < NN) { g_colcnt[i] = 0; g_rowcnt[i] = 0; g_cursor[i] = 0; }
}

__global__ void coordinit_kernel(const float* __restrict__ ci) {
    int i = blockIdx.x * blockDim.x + threadIdx.x;
    if (i < NN * 3) g_coord[i] = ci[i];
}

__global__ void hist_kernel(const void* __restrict__ ei) {
    int e = blockIdx.x * blockDim.x + threadIdx.x;
    int is64 = g_is64;
    if (e < EE) {
        atomicAdd(&g_rowcnt[eidx(ei, e, is64)], 1);
        atomicAdd(&g_colcnt[eidx(ei, (long long)EE + e, is64)], 1);
    }
}

__global__ void cntf_kernel() {
    int n = blockIdx.x * blockDim.x + threadIdx.x;
    if (n < NN) g_cntf[n] = fmaxf(1.f, (float)g_rowcnt[n]);
}

__global__ void scan_kernel() {
    const int BPT = 10;
    int t = threadIdx.x;
    int loc[BPT];
    int s = 0;
#pragma unroll
    for (int j = 0; j < BPT; j++) {
        int b = t * BPT + j;
        int v = (b < NN) ? g_colcnt[b] : 0;
        loc[j] = s; s += v;
    }
    unsigned full = 0xffffffffu;
    int lane = t & 31, wid = t >> 5;
    int v = s;
#pragma unroll
    for (int o = 1; o < 32; o <<= 1) {
        int u = __shfl_up_sync(full, v, o);
        if (lane >= o) v += u;
    }
    __shared__ int wsum[32];
    if (lane == 31) wsum[wid] = v;
    __syncthreads();
    if (wid == 0) {
        int x = wsum[lane];
#pragma unroll
        for (int o = 1; o < 32; o <<= 1) {
            int u = __shfl_up_sync(full, x, o);
            if (lane >= o) x += u;
        }
        wsum[lane] = x;
    }
    __syncthreads();
    int excl = v - s + (wid ? wsum[wid - 1] : 0);
#pragma unroll
    for (int j = 0; j < BPT; j++) {
        int b = t * BPT + j;
        if (b < NN) g_colstart[b] = excl + loc[j];
    }
    if (t == 1023) g_colstart[NN] = wsum[31];
}

__global__ void scatter_kernel(const void* __restrict__ ei) {
    int e = blockIdx.x * blockDim.x + threadIdx.x;
    if (e < EE) {
        int c = eidx(ei, (long long)EE + e, g_is64);
        int p = atomicAdd(&g_cursor[c], 1);
        g_perm[g_colstart[c] + p] = e;
    }
}

// ---------------- model kernels ----------------
__global__ void h0_kernel(const float* __restrict__ x,
                          const float* __restrict__ w, const float* __restrict__ b) {
    int idx = blockIdx.x * blockDim.x + threadIdx.x;
    if (idx >= NN * 32) return;
    int n = idx >> 5, i = idx & 31;
    float acc = b[i];
#pragma unroll
    for (int f = 0; f < 3; f++) acc = fmaf(x[n * 3 + f], w[f * 32 + i], acc);
    g_h[idx] = acc;
}

// Precompute tf32 splits of W2 once.
__global__ void w2split_kernel(const float* __restrict__ w2) {
    int i = blockIdx.x * blockDim.x + threadIdx.x;
    if (i < 128 * 256) {
        float v = w2[i];
        float b = tf32r(v);
        g_w2b[i] = b;
        g_w2s[i] = tf32r(v - b);
    }
}

// Precompute tf32 splits of ker3 once, in [j][ci] stage layout (layer-invariant).
__global__ void k3split_kernel(const float* __restrict__ k3w) {
    int i = blockIdx.x * blockDim.x + threadIdx.x;
    if (i >= 32 * 8192) return;
    int j = i >> 13, ci = i & 8191;
    float v = k3w[(size_t)(ci >> 5) * 1024 + (ci & 31) * 32 + j];
    float b = tf32r(v);
    g_k3b[(size_t)j * 8192 + ci] = b;
    g_k3s[(size_t)j * 8192 + ci] = tf32r(v - b);
}

// k2 v4: 64 edges x 256 cols per block (w2 staging traffic halved vs v3).
// Warp tile: 32 edge-rows x 64 cols. acc[2][8][4].
#define K2_SMEM_FLOATS 19520
__global__ void __launch_bounds__(256) k2_mma_kernel(
    const float* __restrict__ ea,
    const float* __restrict__ w1, const float* __restrict__ b1,
    const float* __restrict__ b2)
{
    extern __shared__ float sk[];
    float* w2b_s = sk;             // 16*264 = 4224
    float* w2s_s = sk + 4224;      // 4224
    float* kt    = sk;             // 32*260 = 8320 (reuses w2 region after MMA)
    float* As_b  = sk + 8448;      // 64*20 = 1280
    float* As_s  = sk + 9728;      // 1280
    float* t1f   = sk + 11008;     // 64*129 = 8256
    float* b2s   = sk + 19264;     // 256

    int e0 = blockIdx.x * 64;
    int tid = threadIdx.x;

    if (tid < 256) b2s[tid] = b2[tid];
    for (int idx = tid; idx < 64 * 128; idx += 256) {
        int el = idx >> 7, j = idx & 127;
        int e = e0 + el;
        float acc = 0.f;
        if (e < EE) {
            acc = b1[j];
#pragma unroll
            for (int f = 0; f < 6; f++) acc = fmaf(ea[e * 6 + f], w1[f * 128 + j], acc);
        }
        t1f[el * 129 + j] = fmaxf(acc, 0.f);
    }

    int w = tid >> 5, lane = tid & 31;
    int g = lane >> 2, tig = lane & 3;
    int wm2 = w & 1;      // edge 32-half
    int wn = w >> 1;      // 4 col-groups of 64

    float acc[2][8][4] = {};

#pragma unroll 1
    for (int kb = 0; kb < 8; kb++) {
        __syncthreads();
        for (int idx = tid; idx < 1024; idx += 256) {
            int r = idx >> 6, q = idx & 63;
            cp_async16(w2b_s + r * 264 + q * 4, g_w2b + (kb * 16 + r) * 256 + q * 4);
            cp_async16(w2s_s + r * 264 + q * 4, g_w2s + (kb * 16 + r) * 256 + q * 4);
        }
        CP_COMMIT();
        for (int idx = tid; idx < 1024; idx += 256) {
            int el = idx >> 4, kl = idx & 15;
            float v = t1f[el * 129 + kb * 16 + kl];
            float b = tf32r(v);
            As_b[el * 20 + kl] = b;
            As_s[el * 20 + kl] = tf32r(v - b);
        }
        CP_WAIT(0);
        __syncthreads();

#pragma unroll
        for (int ks = 0; ks < 2; ks++) {
            int kk = ks * 8;
            unsigned ab[2][4], asr[2][4];
#pragma unroll
            for (int mi = 0; mi < 2; mi++) {
                int r0 = wm2 * 32 + mi * 16 + g;
                ab[mi][0]  = __float_as_uint(As_b[r0 * 20 + kk + tig]);
                ab[mi][1]  = __float_as_uint(As_b[(r0 + 8) * 20 + kk + tig]);
                ab[mi][2]  = __float_as_uint(As_b[r0 * 20 + kk + tig + 4]);
                ab[mi][3]  = __float_as_uint(As_b[(r0 + 8) * 20 + kk + tig + 4]);
                asr[mi][0] = __float_as_uint(As_s[r0 * 20 + kk + tig]);
                asr[mi][1] = __float_as_uint(As_s[(r0 + 8) * 20 + kk + tig]);
                asr[mi][2] = __float_as_uint(As_s[r0 * 20 + kk + tig + 4]);
                asr[mi][3] = __float_as_uint(As_s[(r0 + 8) * 20 + kk + tig + 4]);
            }
#pragma unroll
            for (int ni = 0; ni < 8; ni++) {
                int c0l = wn * 64 + ni * 8 + g;
                unsigned bb[2], bsr[2];
                bb[0]  = __float_as_uint(w2b_s[(kk + tig) * 264 + c0l]);
                bb[1]  = __float_as_uint(w2b_s[(kk + tig + 4) * 264 + c0l]);
                bsr[0] = __float_as_uint(w2s_s[(kk + tig) * 264 + c0l]);
                bsr[1] = __float_as_uint(w2s_s[(kk + tig + 4) * 264 + c0l]);
#pragma unroll
                for (int mi = 0; mi < 2; mi++) {
                    mma_tf32(acc[mi][ni], ab[mi], bb);
                    mma_tf32(acc[mi][ni], ab[mi], bsr);
                    mma_tf32(acc[mi][ni], asr[mi], bb);
                }
            }
        }
    }

    // two-phase staged writeout (32 edge-rows per phase)
#pragma unroll 1
    for (int ph = 0; ph < 2; ph++) {
        __syncthreads();
        if (wm2 == ph) {
#pragma unroll
            for (int mi = 0; mi < 2; mi++) {
                int r = mi * 16 + g;
#pragma unroll
                for (int ni = 0; ni < 8; ni++) {
                    int col = wn * 64 + ni * 8 + 2 * tig;
                    kt[r * 260 + col]           = acc[mi][ni][0];
                    kt[r * 260 + col + 1]       = acc[mi][ni][1];
                    kt[(r + 8) * 260 + col]     = acc[mi][ni][2];
                    kt[(r + 8) * 260 + col + 1] = acc[mi][ni][3];
                }
            }
        }
        __syncthreads();
        for (int idx = tid; idx < 8192; idx += 256) {
            int row = idx >> 8, col = idx & 255;
            int e = e0 + ph * 32 + row;
            if (e < EE) {
                float v = fmaxf(kt[row * 260 + col] + b2s[col], 0.f);
                g_k2[(size_t)e * 256 + col] = v;
            }
        }
    }
}

// G2 v3: ci-outer. Block = 64-ci chunk x node quarter; bk staged ONCE per
// block; loops 64-node chunks (h stays L2-hot).
#define G_NODES_PER_X ((NN + 3) / 4)
__global__ void __launch_bounds__(256) G_mma_kernel() {
    __shared__ float hs_b[64 * 36], hs_s[64 * 36];
    __shared__ float bk_b[32 * 72], bk_s[32 * 72];
    __shared__ float Gt[64 * 65];

    int ci0 = blockIdx.y * 64;
    int nstart = blockIdx.x * G_NODES_PER_X;
    int nend = min(nstart + G_NODES_PER_X, NN);
    int tid = threadIdx.x;

    // stage bk once
    for (int idx = tid; idx < 512; idx += 256) {
        int r = idx >> 4, q = idx & 15;
        cp_async16(bk_b + r * 72 + q * 4, g_k3b + (size_t)r * 8192 + ci0 + q * 4);
        cp_async16(bk_s + r * 72 + q * 4, g_k3s + (size_t)r * 8192 + ci0 + q * 4);
    }
    CP_COMMIT();
    CP_WAIT(0);

    int w = tid >> 5, lane = tid & 31;
    int g = lane >> 2, tig = lane & 3;
    int wm = w & 1, wn = w >> 1;

#pragma unroll 1
    for (int nb = nstart; nb < nend; nb += 64) {
        __syncthreads();   // bk visible (first); prior hs readers + Gt writers done
        for (int idx = tid; idx < 2048; idx += 256) {
            int nl = idx >> 5, j = idx & 31;
            int n = nb + nl;
            float v = (n < nend) ? g_h[n * 32 + j] : 0.f;
            float b = tf32r(v);
            hs_b[nl * 36 + j] = b;
            hs_s[nl * 36 + j] = tf32r(v - b);
        }
        __syncthreads();

        float acc[2][2][4] = {};
#pragma unroll
        for (int ks = 0; ks < 4; ks++) {
            int kk = ks * 8;
            unsigned ab[2][4], asr[2][4], bb[2][2], bsr[2][2];
#pragma unroll
            for (int mi = 0; mi < 2; mi++) {
                int r0 = wm * 32 + mi * 16 + g;
                ab[mi][0]  = __float_as_uint(hs_b[r0 * 36 + kk + tig]);
                ab[mi][1]  = __float_as_uint(hs_b[(r0 + 8) * 36 + kk + tig]);
                ab[mi][2]  = __float_as_uint(hs_b[r0 * 36 + kk + tig + 4]);
                ab[mi][3]  = __float_as_uint(hs_b[(r0 + 8) * 36 + kk + tig + 4]);
                asr[mi][0] = __float_as_uint(hs_s[r0 * 36 + kk + tig]);
                asr[mi][1] = __float_as_uint(hs_s[(r0 + 8) * 36 + kk + tig]);
                asr[mi][2] = __float_as_uint(hs_s[r0 * 36 + kk + tig + 4]);
                asr[mi][3] = __float_as_uint(hs_s[(r0 + 8) * 36 + kk + tig + 4]);
            }
#pragma unroll
            for (int ni = 0; ni < 2; ni++) {
                int c0l = wn * 16 + ni * 8 + g;
                bb[ni][0]  = __float_as_uint(bk_b[(kk + tig) * 72 + c0l]);
                bb[ni][1]  = __float_as_uint(bk_b[(kk + tig + 4) * 72 + c0l]);
                bsr[ni][0] = __float_as_uint(bk_s[(kk + tig) * 72 + c0l]);
                bsr[ni][1] = __float_as_uint(bk_s[(kk + tig + 4) * 72 + c0l]);
            }
#pragma unroll
            for (int mi = 0; mi < 2; mi++)
#pragma unroll
                for (int ni = 0; ni < 2; ni++) {
                    mma_tf32(acc[mi][ni], ab[mi], bb[ni]);
                    mma_tf32(acc[mi][ni], ab[mi], bsr[ni]);
                    mma_tf32(acc[mi][ni], asr[mi], bb[ni]);
                }
        }

#pragma unroll
        for (int mi = 0; mi < 2; mi++) {
            int rl = wm * 32 + mi * 16 + g;
#pragma unroll
            for (int ni = 0; ni < 2; ni++) {
                int cl = wn * 16 + ni * 8 + 2 * tig;
                Gt[rl * 65 + cl]           = acc[mi][ni][0];
                Gt[rl * 65 + cl + 1]       = acc[mi][ni][1];
                Gt[(rl + 8) * 65 + cl]     = acc[mi][ni][2];
                Gt[(rl + 8) * 65 + cl + 1] = acc[mi][ni][3];
            }
        }
        __syncthreads();
        for (int idx = tid; idx < 4096; idx += 256) {
            int row = idx >> 6, col = idx & 63;
            int n = nb + row;
            if (n < nend) g_G2[(size_t)n * 8192 + ci0 + col] = Gt[row * 65 + col];
        }
    }
}

// Bias[n][i] = sum_j ker3_b[i*32+j] * h[n][j] (exact fp32); zero agg/cacc.
__global__ void bias_zero_kernel(const float* __restrict__ b3) {
    int idx = blockIdx.x * blockDim.x + threadIdx.x;
    if (idx < NN * 3) g_cacc[idx] = 0.f;
    if (idx >= NN * 32) return;
    int n = idx >> 5, i = idx & 31;
    float acc = 0.f;
#pragma unroll
    for (int j = 0; j < 32; j++) acc = fmaf(b3[i * 32 + j], g_h[n * 32 + j], acc);
    g_Bias[idx] = acc;
    g_agg[idx] = 0.f;
}

// Edge kernel v4: single G buffer; async G2 load overlapped with k2/es staging.
#define SMEM_EDGE_FLOATS 18884
__global__ void __launch_bounds__(256) edge_kernel(
    const void* __restrict__ ei,
    const float* __restrict__ cm1w, const float* __restrict__ cm1b,
    const float* __restrict__ cm2w, const float* __restrict__ cm2b)
{
    extern __shared__ float sm[];
    float* Gs    = sm;                  // 8192
    float* k2s   = sm + 8192;           // 32*260 = 8320
    float* cm1s  = sm + 16512;          // 32*33 = 1056
    float* ms_   = sm + 17568;          // 32*36 = 1152
    float* Bs    = sm + 18720;          // 32
    float* cm1bs = sm + 18752;          // 32
    float* cm2s  = sm + 18784;          // 32
    int*   es    = (int*)(sm + 18816);  // 32
    int*   rs    = (int*)(sm + 18848);  // 32
    float* ccolp = sm + 18880;          // [0..2]=ccol, [3]=cm2b0

    int tid = threadIdx.x, w = tid >> 5, lane = tid & 31;
    int is64 = g_is64;
    int n0 = blockIdx.x * NPB;

    for (int idx = tid; idx < 1024; idx += 256)
        cm1s[(idx >> 5) * 33 + (idx & 31)] = cm1w[idx];
    if (tid < 32) { cm1bs[tid] = cm1b[tid]; cm2s[tid] = cm2w[tid]; }
    if (tid == 0) ccolp[3] = cm2b[0];

    int lg = lane >> 3;
    int iq = lane & 7;
    const unsigned full = 0xffffffffu;

#pragma unroll 1
    for (int t = 0; t < NPB; t++) {
        int n = n0 + t;
        {
            const float* src = g_G2 + (size_t)n * 8192;
            for (int idx = tid; idx < 2048; idx += 256)
                cp_async16(Gs + idx * 4, src + idx * 4);
            CP_COMMIT();
        }
        if (tid < 32) Bs[tid] = g_Bias[n * 32 + tid];
        if (tid < 3) ccolp[tid] = g_coord[n * 3 + tid];

        int cs0 = g_colstart[n];
        int deg = g_colstart[n + 1] - cs0;

        for (int base = 0; base < deg; base += 32) {
            if (base) __syncthreads();
            if (tid < 32) {
                int p = base + tid;
                int e = (p < deg) ? g_perm[cs0 + p] : -1;
                es[tid] = e;
                rs[tid] = (e >= 0) ? eidx(ei, e, is64) : 0;
            }
            __syncthreads();
            for (int idx = tid; idx < 2048; idx += 256) {
                int el = idx >> 6, c4 = idx & 63;
                int e = es[el];
                float4 v = (e >= 0) ? ((const float4*)g_k2)[(size_t)e * 64 + c4]
                                    : make_float4(0.f, 0.f, 0.f, 0.f);
                *(float4*)&k2s[el * 260 + c4 * 4] = v;
            }
            if (base == 0) CP_WAIT(0);
            __syncthreads();

            int e_l0 = w * 4;
            float acc[4][4] = {};
            const float4* G4 = (const float4*)Gs;
#pragma unroll 4
            for (int cb = 0; cb < 64; cb++) {
                int c = cb * 4 + lg;
                float4 gv = G4[c * 8 + iq];
                float k0 = k2s[(e_l0 + 0) * 260 + c];
                float k1 = k2s[(e_l0 + 1) * 260 + c];
                float k2v = k2s[(e_l0 + 2) * 260 + c];
                float k3 = k2s[(e_l0 + 3) * 260 + c];
                acc[0][0] = fmaf(k0, gv.x, acc[0][0]); acc[0][1] = fmaf(k0, gv.y, acc[0][1]);
                acc[0][2] = fmaf(k0, gv.z, acc[0][2]); acc[0][3] = fmaf(k0, gv.w, acc[0][3]);
                acc[1][0] = fmaf(k1, gv.x, acc[1][0]); acc[1][1] = fmaf(k1, gv.y, acc[1][1]);
                acc[1][2] = fmaf(k1, gv.z, acc[1][2]); acc[1][3] = fmaf(k1, gv.w, acc[1][3]);
                acc[2][0] = fmaf(k2v, gv.x, acc[2][0]); acc[2][1] = fmaf(k2v, gv.y, acc[2][1]);
                acc[2][2] = fmaf(k2v, gv.z, acc[2][2]); acc[2][3] = fmaf(k2v, gv.w, acc[2][3]);
                acc[3][0] = fmaf(k3, gv.x, acc[3][0]); acc[3][1] = fmaf(k3, gv.y, acc[3][1]);
                acc[3][2] = fmaf(k3, gv.z, acc[3][2]); acc[3][3] = fmaf(k3, gv.w, acc[3][3]);
            }
#pragma unroll
            for (int q = 0; q < 4; q++)
#pragma unroll
                for (int c = 0; c < 4; c++) {
                    acc[q][c] += __shfl_xor_sync(full, acc[q][c], 8);
                    acc[q][c] += __shfl_xor_sync(full, acc[q][c], 16);
                }
            if (lane < 8) {
#pragma unroll
                for (int q = 0; q < 4; q++)
                    *(float4*)&ms_[(e_l0 + q) * 36 + iq * 4] =
                        make_float4(acc[q][0], acc[q][1], acc[q][2], acc[q][3]);
            }
            __syncwarp();
#pragma unroll
            for (int q = 0; q < 4; q++) {
                int el = e_l0 + q;
                float mf = ms_[el * 36 + lane] + Bs[lane];
                ms_[el * 36 + lane] = mf;
                if (es[el] >= 0) atomicAdd(&g_agg[rs[el] * 32 + lane], mf);
            }
            __syncwarp();
#pragma unroll 1
            for (int q = 0; q < 4; q++) {
                int el = e_l0 + q;
                float tt = cm1bs[lane];
#pragma unroll
                for (int i = 0; i < 32; i++)
                    tt = fmaf(ms_[el * 36 + i], cm1s[i * 33 + lane], tt);
                tt = fmaxf(tt, 0.f) * cm2s[lane];
#pragma unroll
                for (int off = 16; off; off >>= 1) tt += __shfl_xor_sync(full, tt, off);
                int e = es[el];
                if (e >= 0 && lane < 3) {
                    float we = tt + ccolp[3];
                    int r = rs[el];
                    atomicAdd(&g_cacc[r * 3 + lane], (g_coord[r * 3 + lane] - ccolp[lane]) * we);
                }
            }
        }
        __syncthreads();
    }
}

__global__ void node_kernel() {
    int idx = blockIdx.x * blockDim.x + threadIdx.x;
    if (idx >= NN * 32) return;
    int n = idx >> 5, i = idx & 31;
    float cf = g_cntf[n];
    float hv = g_h[idx] + g_agg[idx] / cf;
    g_h[idx] = fmaxf(hv, 0.f);
    if (i < 3) g_coord[n * 3 + i] += g_cacc[n * 3 + i] / cf;
}

__global__ void out_kernel(const float* __restrict__ aw, const float* __restrict__ ab,
                           const float* __restrict__ bw, const float* __restrict__ bb,
                           float* __restrict__ out, int out_size) {
    int n = blockIdx.x * blockDim.x + threadIdx.x;
    if (n >= NN) return;
    float h[32];
    const float4* hp = (const float4*)(g_h + n * 32);
#pragma unroll
    for (int q = 0; q < 8; q++) {
        float4 v = hp[q];
        h[q * 4] = v.x; h[q * 4 + 1] = v.y; h[q * 4 + 2] = v.z; h[q * 4 + 3] = v.w;
    }
    float acc = bb[0];
#pragma unroll 4
    for (int j = 0; j < 64; j++) {
        float t = ab[j];
#pragma unroll
        for (int i = 0; i < 32; i++) t = fmaf(h[i], aw[i * 64 + j], t);
        acc = fmaf(fmaxf(t, 0.f), bw[j], acc);
    }
    out[n] = acc;
#pragma unroll
    for (int d = 0; d < 3; d++) {
        int idx = NN + n * 3 + d;
        if (idx < out_size) out[idx] = g_coord[n * 3 + d];
    }
}

// ---------------- launch ----------------
extern "C" void kernel_launch(void* const* d_in, const int* in_sizes, int n_in,
                              void* d_out, int out_size) {
    const float* x      = (const float*)d_in[0];
    const void*  ei     = d_in[1];
    const float* ea     = (const float*)d_in[2];
    const float* ci     = (const float*)d_in[3];
    const float* fc1w   = (const float*)d_in[4];
    const float* fc1b   = (const float*)d_in[5];
    const float* k1w    = (const float*)d_in[6];
    const float* k1b    = (const float*)d_in[7];
    const float* k2w    = (const float*)d_in[8];
    const float* k2b    = (const float*)d_in[9];
    const float* k3w    = (const float*)d_in[10];
    const float* k3b    = (const float*)d_in[11];
    const float* cm1w   = (const float*)d_in[12];
    const float* cm1b   = (const float*)d_in[13];
    const float* cm2w   = (const float*)d_in[14];
    const float* cm2b   = (const float*)d_in[15];
    const float* fc2aw  = (const float*)d_in[16];
    const float* fc2ab  = (const float*)d_in[17];
    const float* fc2bw  = (const float*)d_in[18];
    const float* fc2bb  = (const float*)d_in[19];
    float* out = (float*)d_out;

    cudaFuncSetAttribute(edge_kernel, cudaFuncAttributeMaxDynamicSharedMemorySize,
                         SMEM_EDGE_FLOATS * 4);
    cudaFuncSetAttribute(k2_mma_kernel, cudaFuncAttributeMaxDynamicSharedMemorySize,
                         K2_SMEM_FLOATS * 4);

    // Slot 4 = layer-0 G_mma v3 (profiler capture window).
    detect_kernel<<<1, 32>>>(ei);
    k3split_kernel<<<(32 * 8192 + 255) / 256, 256>>>(k3w);
    h0_kernel<<<(NN * 32 + 255) / 256, 256>>>(x, fc1w, fc1b);
    G_mma_kernel<<<dim3(4, 128), 256>>>();
    zero_sort_kernel<<<(NN + 255) / 256, 256>>>();
    hist_kernel<<<(EE + 255) / 256, 256>>>(ei);
    scan_kernel<<<1, 1024>>>();
    cntf_kernel<<<(NN + 255) / 256, 256>>>();
    scatter_kernel<<<(EE + 255) / 256, 256>>>(ei);
    coordinit_kernel<<<(NN * 3 + 255) / 256, 256>>>(ci);
    w2split_kernel<<<128, 256>>>(k2w);
    k2_mma_kernel<<<(EE + 63) / 64, 256, K2_SMEM_FLOATS * 4>>>(ea, k1w, k1b, k2b);

    for (int layer = 0; layer < 4; layer++) {
        if (layer > 0)
            G_mma_kernel<<<dim3(4, 128), 256>>>();
        bias_zero_kernel<<<(NN * 32 + 255) / 256, 256>>>(k3b);
        edge_kernel<<<NN / NPB, 256, SMEM_EDGE_FLOATS * 4>>>(ei, cm1w, cm1b, cm2w, cm2b);
        node_kernel<<<(NN * 32 + 255) / 256, 256>>>();
    }

    out_kernel<<<(NN + 255) / 256, 256>>>(fc2aw, fc2ab, fc2bw, fc2bb, out, out_size);
}